// round 2
// baseline (speedup 1.0000x reference)
#include <cuda_runtime.h>
#include <cstdint>

#define NN 100000
#define EE 800000

// ---------------- device scratch (static: no allocations allowed) ----------------
__device__ __align__(16) float    g_h[NN * 128];     // h = x @ W        [N,128]
__device__ __align__(16) float    g_out[NN * 128];   // aggregation acc  [N,128]
__device__ __align__(16) float    g_x1[NN * 128];    // inter-layer x
__device__ __align__(16) float    g_asrc[NN * 4];
__device__ __align__(16) float    g_adst[NN * 4];
__device__ __align__(16) float    g_mf[NN * 4];      // segment max (decoded)
__device__ __align__(16) float    g_s[NN * 4];       // segment expsum
__device__ __align__(16) float    g_eloop[NN * 4];   // self-loop e value
__device__ __align__(16) unsigned g_menc[NN * 4];    // encoded max for atomicMax
__device__ __align__(16) float    g_ebuf[EE * 4];    // per-edge e / exp(e-m)

// ---------------- helpers ----------------
__device__ __forceinline__ float lrelu(float v) { return v > 0.f ? v : 0.2f * v; }

// monotone float<->uint encoding so unsigned atomicMax == float max
__device__ __forceinline__ unsigned fenc(float f) {
    unsigned u = __float_as_uint(f);
    return (u & 0x80000000u) ? ~u : (u | 0x80000000u);
}
__device__ __forceinline__ float fdec(unsigned u) {
    return __uint_as_float((u & 0x80000000u) ? (u & 0x7fffffffu) : ~u);
}

// vectorized fire-and-forget global reduction (sm_90+)
__device__ __forceinline__ void red_add_v4(float4* addr, float4 v) {
    asm volatile("red.global.add.v4.f32 [%0], {%1, %2, %3, %4};"
                 :: "l"(addr), "f"(v.x), "f"(v.y), "f"(v.z), "f"(v.w)
                 : "memory");
}

// ---------------- 1) GEMM: g_h = X @ W  (Mx128x128 fp32) ----------------
// 128x128 block tile, full K=128 resident, 8x8 register tile per thread.
__global__ __launch_bounds__(256) void k_gemm(const float* __restrict__ X,
                                              const float* __restrict__ W) {
    extern __shared__ float sm[];
    float* ws = sm;           // [128][128]  ws[k*128+col]
    float* xs = sm + 16384;   // [128][129]  xs[k*129+row]  (pad: conflict-free)
    const int tx = threadIdx.x;          // 0..15 col group
    const int ty = threadIdx.y;          // 0..15 row group
    const int tid = ty * 16 + tx;
    const int row0 = blockIdx.x * 128;

    // load W (16384 floats) vectorized
    const float4* W4 = (const float4*)W;
    float4* ws4 = (float4*)ws;
#pragma unroll 4
    for (int i = tid; i < 4096; i += 256) ws4[i] = W4[i];

    // load X tile transposed: xs[k][row]
    for (int i = tid; i < 16384; i += 256) {
        int r = i >> 7, k = i & 127;
        int row = row0 + r;
        xs[k * 129 + r] = (row < NN) ? X[row * 128 + k] : 0.f;
    }
    __syncthreads();

    float acc[8][8];
#pragma unroll
    for (int i = 0; i < 8; i++)
#pragma unroll
        for (int j = 0; j < 8; j++) acc[i][j] = 0.f;

    const int rb = ty * 8, cb = tx * 8;
#pragma unroll 8
    for (int k = 0; k < 128; k++) {
        float xv[8];
#pragma unroll
        for (int i = 0; i < 8; i++) xv[i] = xs[k * 129 + rb + i];
        float4 w0 = *(const float4*)&ws[k * 128 + cb];
        float4 w1 = *(const float4*)&ws[k * 128 + cb + 4];
        float wv[8] = {w0.x, w0.y, w0.z, w0.w, w1.x, w1.y, w1.z, w1.w};
#pragma unroll
        for (int i = 0; i < 8; i++)
#pragma unroll
            for (int j = 0; j < 8; j++) acc[i][j] += xv[i] * wv[j];
    }

#pragma unroll
    for (int i = 0; i < 8; i++) {
        int row = row0 + rb + i;
        if (row < NN) {
            float4 o0 = {acc[i][0], acc[i][1], acc[i][2], acc[i][3]};
            float4 o1 = {acc[i][4], acc[i][5], acc[i][6], acc[i][7]};
            *(float4*)&g_h[row * 128 + cb] = o0;
            *(float4*)&g_h[row * 128 + cb + 4] = o1;
        }
    }
}

// ---------------- 2) per-node attention coeffs + self-loop init ----------------
// one warp per node: a_src/a_dst dot products, e_loop, max init
__global__ void k_natt(const float* __restrict__ att_s, const float* __restrict__ att_d) {
    int t = blockIdx.x * blockDim.x + threadIdx.x;
    int n = t >> 5, lane = t & 31;
    if (n >= NN) return;
    float as[4], ad[4];
#pragma unroll
    for (int i = 0; i < 4; i++) {
        float hv = g_h[n * 128 + i * 32 + lane];
        float ps = hv * att_s[i * 32 + lane];
        float pd = hv * att_d[i * 32 + lane];
#pragma unroll
        for (int o = 16; o; o >>= 1) {
            ps += __shfl_xor_sync(0xffffffff, ps, o);
            pd += __shfl_xor_sync(0xffffffff, pd, o);
        }
        as[i] = ps; ad[i] = pd;
    }
    if (lane == 0) {
#pragma unroll
        for (int i = 0; i < 4; i++) {
            g_asrc[n * 4 + i] = as[i];
            g_adst[n * 4 + i] = ad[i];
            float el = lrelu(as[i] + ad[i]);
            g_eloop[n * 4 + i] = el;
            g_menc[n * 4 + i] = fenc(el);  // self-loop initializes the segment max
        }
    }
}

// ---------------- 3) per-edge e + segment max ----------------
__global__ void k_edge_max(const int* __restrict__ ei) {
    int e = blockIdx.x * blockDim.x + threadIdx.x;
    if (e >= EE) return;
    int s = ei[e], d = ei[EE + e];
    float4 a = ((const float4*)g_asrc)[s];
    float4 b = ((const float4*)g_adst)[d];
    float e0 = lrelu(a.x + b.x), e1 = lrelu(a.y + b.y);
    float e2 = lrelu(a.z + b.z), e3 = lrelu(a.w + b.w);
    ((float4*)g_ebuf)[e] = make_float4(e0, e1, e2, e3);
    unsigned* m = &g_menc[d * 4];
    atomicMax(m + 0, fenc(e0));
    atomicMax(m + 1, fenc(e1));
    atomicMax(m + 2, fenc(e2));
    atomicMax(m + 3, fenc(e3));
}

// ---------------- 4) decode max, init expsum with self-loop ----------------
__global__ void k_node_fin1() {
    int n = blockIdx.x * blockDim.x + threadIdx.x;
    if (n >= NN) return;
    uint4 me = ((const uint4*)g_menc)[n];
    float4 m = make_float4(fdec(me.x), fdec(me.y), fdec(me.z), fdec(me.w));
    ((float4*)g_mf)[n] = m;
    float4 el = ((const float4*)g_eloop)[n];
    ((float4*)g_s)[n] = make_float4(__expf(el.x - m.x), __expf(el.y - m.y),
                                    __expf(el.z - m.z), __expf(el.w - m.w));
}

// ---------------- 5) per-edge exp + segment sum ----------------
__global__ void k_edge_sum(const int* __restrict__ ei) {
    int e = blockIdx.x * blockDim.x + threadIdx.x;
    if (e >= EE) return;
    int d = ei[EE + e];
    float4 m = ((const float4*)g_mf)[d];
    float4 w = ((const float4*)g_ebuf)[e];
    w.x = __expf(w.x - m.x); w.y = __expf(w.y - m.y);
    w.z = __expf(w.z - m.z); w.w = __expf(w.w - m.w);
    ((float4*)g_ebuf)[e] = w;
    red_add_v4(((float4*)g_s) + d, w);
}

// ---------------- 6) init out with self-loop message ----------------
__global__ void k_node_init_out() {
    int idx = blockIdx.x * blockDim.x + threadIdx.x;
    if (idx >= NN * 32) return;
    int n = idx >> 5, q = idx & 31, head = q >> 3;
    float el = g_eloop[n * 4 + head];
    float m  = g_mf[n * 4 + head];
    float s  = g_s[n * 4 + head];
    float al = __expf(el - m) / (s + 1e-16f);
    float4 hv = ((const float4*)g_h)[n * 32 + q];
    hv.x *= al; hv.y *= al; hv.z *= al; hv.w *= al;
    ((float4*)g_out)[n * 32 + q] = hv;
}

// ---------------- 7) edge aggregation: out[dst] += h[src] * alpha ----------------
// one warp per edge; each lane owns one float4 (16B) of the 512B row
__global__ void k_edge_aggr(const int* __restrict__ ei) {
    int t = blockIdx.x * blockDim.x + threadIdx.x;
    int e = t >> 5, lane = t & 31;
    if (e >= EE) return;
    int s = ei[e], d = ei[EE + e];
    int head = lane >> 3;
    float al = g_ebuf[e * 4 + head] / (g_s[d * 4 + head] + 1e-16f);
    float4 v = ((const float4*)g_h)[s * 32 + lane];
    v.x *= al; v.y *= al; v.z *= al; v.w *= al;
    red_add_v4(((float4*)g_out) + d * 32 + lane, v);
}

// ---------------- 8) relu(out + bias) -> next x ----------------
__global__ void k_relu_bias(const float* __restrict__ bias, float* __restrict__ xout) {
    int idx = blockIdx.x * blockDim.x + threadIdx.x;
    if (idx >= NN * 32) return;
    float4 o = ((const float4*)g_out)[idx];
    float4 b = ((const float4*)bias)[idx & 31];
    o.x = fmaxf(o.x + b.x, 0.f); o.y = fmaxf(o.y + b.y, 0.f);
    o.z = fmaxf(o.z + b.z, 0.f); o.w = fmaxf(o.w + b.w, 0.f);
    ((float4*)xout)[idx] = o;
}

// ---------------- host ----------------
extern "C" void kernel_launch(void* const* d_in, const int* in_sizes, int n_in,
                              void* d_out, int out_size) {
    // parse inputs by element count (robust to metadata ordering):
    //   x: 12,800,000 f32 | edge_index: 1,600,000 i32 | W: 16,384 f32 |
    //   att_src/att_dst/bias: 128 f32, per-layer consecutive triples
    const float* x = nullptr;
    const int*   ei[3] = {};
    const float* W[3] = {};
    const float* small[9] = {};
    int nei = 0, nw = 0, ns = 0;
    for (int i = 0; i < n_in; i++) {
        int sz = in_sizes[i];
        if (sz == NN * 128)          x = (const float*)d_in[i];
        else if (sz == 2 * EE)       { if (nei < 3) ei[nei++] = (const int*)d_in[i]; }
        else if (sz == 128 * 128)    { if (nw < 3)  W[nw++]  = (const float*)d_in[i]; }
        else if (sz == 128)          { if (ns < 9)  small[ns++] = (const float*)d_in[i]; }
    }
    const float* asrc[3], *adst[3], *bias[3];
    for (int l = 0; l < 3; l++) {
        asrc[l] = small[l * 3 + 0];
        adst[l] = small[l * 3 + 1];
        bias[l] = small[l * 3 + 2];
    }

    float* x1 = nullptr;
    cudaGetSymbolAddress((void**)&x1, g_x1);
    cudaFuncSetAttribute(k_gemm, cudaFuncAttributeMaxDynamicSharedMemorySize, 131584);

    const int GEMM_BLOCKS = (NN + 127) / 128;      // 782
    const int NTH  = (NN * 32 + 255) / 256;        // node*chunk grids
    const int NB   = (NN + 255) / 256;
    const int EB   = (EE + 255) / 256;
    const int EAGG = (EE * 32 + 255) / 256;        // warp per edge

    const float* xin = x;
    for (int l = 0; l < 3; l++) {
        float* xout = (l == 2) ? (float*)d_out : x1;
        k_gemm<<<GEMM_BLOCKS, dim3(16, 16), 131584>>>(xin, W[l]);
        k_natt<<<NTH, 256>>>(asrc[l], adst[l]);
        k_edge_max<<<EB, 256>>>(ei[l]);
        k_node_fin1<<<NB, 256>>>();
        k_edge_sum<<<EB, 256>>>(ei[l]);
        k_node_init_out<<<NTH, 256>>>();
        k_edge_aggr<<<EAGG, 256>>>(ei[l]);
        k_relu_bias<<<NTH, 256>>>(bias[l], xout);
        xin = xout;
    }
}

// round 3
// speedup vs baseline: 1.2704x; 1.2704x over previous
#include <cuda_runtime.h>
#include <cstdint>

#define NN 100000
#define EE 800000

// ---------------- device scratch (static: no allocations allowed) ----------------
__device__ __align__(16) float g_h[NN * 128];     // h = x @ W        [N,128]
__device__ __align__(16) float g_out[NN * 128];   // unnormalized aggregation acc
__device__ __align__(16) float g_x1[NN * 128];    // inter-layer x
__device__ __align__(16) float g_asrc[NN * 4];    // a_src per node/head
__device__ __align__(16) float g_dn[NN * 8];      // per dst node: {a_dst[4], e_loop[4]} (one 32B sector)
__device__ __align__(16) float g_s[NN * 4];       // softmax denominator acc (excl. self-loop's 1)

// ---------------- helpers ----------------
__device__ __forceinline__ float lrelu(float v) { return v > 0.f ? v : 0.2f * v; }

__device__ __forceinline__ void red_add_v4(float4* addr, float4 v) {
    asm volatile("red.global.add.v4.f32 [%0], {%1, %2, %3, %4};"
                 :: "l"(addr), "f"(v.x), "f"(v.y), "f"(v.z), "f"(v.w)
                 : "memory");
}
__device__ __forceinline__ void red_add_f32(float* addr, float v) {
    asm volatile("red.global.add.f32 [%0], %1;" :: "l"(addr), "f"(v) : "memory");
}

// ---------------- 1) GEMM: g_h = X @ W  (Mx128x128 fp32) ----------------
__global__ __launch_bounds__(256) void k_gemm(const float* __restrict__ X,
                                              const float* __restrict__ W) {
    extern __shared__ float sm[];
    float* ws = sm;           // [128][128]  ws[k*128+col]
    float* xs = sm + 16384;   // [128][129]  xs[k*129+row]  (pad: conflict-free)
    const int tx = threadIdx.x;          // 0..15 col group
    const int ty = threadIdx.y;          // 0..15 row group
    const int tid = ty * 16 + tx;
    const int row0 = blockIdx.x * 128;

    const float4* W4 = (const float4*)W;
    float4* ws4 = (float4*)ws;
#pragma unroll 4
    for (int i = tid; i < 4096; i += 256) ws4[i] = W4[i];

    for (int i = tid; i < 16384; i += 256) {
        int r = i >> 7, k = i & 127;
        int row = row0 + r;
        xs[k * 129 + r] = (row < NN) ? X[row * 128 + k] : 0.f;
    }
    __syncthreads();

    float acc[8][8];
#pragma unroll
    for (int i = 0; i < 8; i++)
#pragma unroll
        for (int j = 0; j < 8; j++) acc[i][j] = 0.f;

    const int rb = ty * 8, cb = tx * 8;
#pragma unroll 8
    for (int k = 0; k < 128; k++) {
        float xv[8];
#pragma unroll
        for (int i = 0; i < 8; i++) xv[i] = xs[k * 129 + rb + i];
        float4 w0 = *(const float4*)&ws[k * 128 + cb];
        float4 w1 = *(const float4*)&ws[k * 128 + cb + 4];
        float wv[8] = {w0.x, w0.y, w0.z, w0.w, w1.x, w1.y, w1.z, w1.w};
#pragma unroll
        for (int i = 0; i < 8; i++)
#pragma unroll
            for (int j = 0; j < 8; j++) acc[i][j] += xv[i] * wv[j];
    }

#pragma unroll
    for (int i = 0; i < 8; i++) {
        int row = row0 + rb + i;
        if (row < NN) {
            float4 o0 = {acc[i][0], acc[i][1], acc[i][2], acc[i][3]};
            float4 o1 = {acc[i][4], acc[i][5], acc[i][6], acc[i][7]};
            *(float4*)&g_h[row * 128 + cb] = o0;
            *(float4*)&g_h[row * 128 + cb + 4] = o1;
        }
    }
}

// ---------------- 2) node prep: attention coeffs + accumulator init ----------------
// One warp per node. Computes a_src/a_dst/e_loop, initializes out with the
// self-loop message h (weight exp(e_loop - e_loop) == 1), zeroes s.
__global__ void k_prep(const float* __restrict__ att_s, const float* __restrict__ att_d) {
    int t = blockIdx.x * blockDim.x + threadIdx.x;
    int n = t >> 5, lane = t & 31;
    if (n >= NN) return;
    int head = lane >> 3;          // float4 chunk q=lane covers head q>>3

    float4 hv = ((const float4*)g_h)[n * 32 + lane];
    float4 av = ((const float4*)att_s)[lane];
    float4 dv = ((const float4*)att_d)[lane];
    float ps = hv.x * av.x + hv.y * av.y + hv.z * av.z + hv.w * av.w;
    float pd = hv.x * dv.x + hv.y * dv.y + hv.z * dv.z + hv.w * dv.w;
    // reduce within each 8-lane head group
#pragma unroll
    for (int o = 4; o; o >>= 1) {
        ps += __shfl_xor_sync(0xffffffff, ps, o);
        pd += __shfl_xor_sync(0xffffffff, pd, o);
    }
    if ((lane & 7) == 0) {
        g_asrc[n * 4 + head] = ps;
        g_dn[n * 8 + head] = pd;
        g_dn[n * 8 + 4 + head] = lrelu(ps + pd);   // e_loop (softmax shift)
    }
    if (lane == 0) ((float4*)g_s)[n] = make_float4(0.f, 0.f, 0.f, 0.f);
    ((float4*)g_out)[n * 32 + lane] = hv;          // self-loop message, weight 1
}

// ---------------- 3) single edge pass: w = exp(lrelu(as+ad)-eloop); s += w; out += w*h ----------------
// One warp per edge; each lane owns one float4 (16B) of the 512B h row.
__global__ void k_edge(const int* __restrict__ ei) {
    int t = blockIdx.x * blockDim.x + threadIdx.x;
    int e = t >> 5, lane = t & 31;
    if (e >= EE) return;
    int s = __ldg(ei + e), d = __ldg(ei + EE + e);
    int head = lane >> 3;

    float as = __ldg(&g_asrc[s * 4 + head]);
    float ad = __ldg(&g_dn[d * 8 + head]);
    float el = __ldg(&g_dn[d * 8 + 4 + head]);
    float w = __expf(lrelu(as + ad) - el);

    if ((lane & 7) == 0) red_add_f32(&g_s[d * 4 + head], w);

    float4 v = ((const float4*)g_h)[s * 32 + lane];
    v.x *= w; v.y *= w; v.z *= w; v.w *= w;
    red_add_v4(((float4*)g_out) + d * 32 + lane, v);
}

// ---------------- 4) finish: x_next = relu(out / (s+1) + bias) ----------------
__global__ void k_finish(const float* __restrict__ bias, float* __restrict__ xout) {
    int idx = blockIdx.x * blockDim.x + threadIdx.x;
    if (idx >= NN * 32) return;
    int n = idx >> 5, q = idx & 31, head = q >> 3;
    float denom = g_s[n * 4 + head] + 1.0f;   // +1 = self-loop weight
    float inv = 1.0f / denom;
    float4 o = ((const float4*)g_out)[idx];
    float4 b = ((const float4*)bias)[q];
    o.x = fmaxf(o.x * inv + b.x, 0.f); o.y = fmaxf(o.y * inv + b.y, 0.f);
    o.z = fmaxf(o.z * inv + b.z, 0.f); o.w = fmaxf(o.w * inv + b.w, 0.f);
    ((float4*)xout)[idx] = o;
}

// ---------------- host ----------------
extern "C" void kernel_launch(void* const* d_in, const int* in_sizes, int n_in,
                              void* d_out, int out_size) {
    const float* x = nullptr;
    const int*   ei[3] = {};
    const float* W[3] = {};
    const float* small[9] = {};
    int nei = 0, nw = 0, ns = 0;
    for (int i = 0; i < n_in; i++) {
        int sz = in_sizes[i];
        if (sz == NN * 128)          x = (const float*)d_in[i];
        else if (sz == 2 * EE)       { if (nei < 3) ei[nei++] = (const int*)d_in[i]; }
        else if (sz == 128 * 128)    { if (nw < 3)  W[nw++]  = (const float*)d_in[i]; }
        else if (sz == 128)          { if (ns < 9)  small[ns++] = (const float*)d_in[i]; }
    }
    const float* asrc[3], *adst[3], *bias[3];
    for (int l = 0; l < 3; l++) {
        asrc[l] = small[l * 3 + 0];
        adst[l] = small[l * 3 + 1];
        bias[l] = small[l * 3 + 2];
    }

    float* x1 = nullptr;
    cudaGetSymbolAddress((void**)&x1, g_x1);
    cudaFuncSetAttribute(k_gemm, cudaFuncAttributeMaxDynamicSharedMemorySize, 131584);

    const int GEMM_BLOCKS = (NN + 127) / 128;       // 782
    const int NWARP = (NN * 32 + 255) / 256;        // warp-per-node grids
    const int EWARP = (EE * 32 + 255) / 256;        // warp-per-edge grid
    const int NELT  = (NN * 32 + 255) / 256;        // float4-per-thread node grid

    const float* xin = x;
    for (int l = 0; l < 3; l++) {
        float* xout = (l == 2) ? (float*)d_out : x1;
        k_gemm<<<GEMM_BLOCKS, dim3(16, 16), 131584>>>(xin, W[l]);
        k_prep<<<NWARP, 256>>>(asrc[l], adst[l]);
        k_edge<<<EWARP, 256>>>(ei[l]);
        k_finish<<<NELT, 256>>>(bias[l], xout);
        xin = xout;
    }
}

// round 4
// speedup vs baseline: 1.2758x; 1.0042x over previous
#include <cuda_runtime.h>
#include <cstdint>

#define NN 100000
#define EE 800000

// ---------------- device scratch ----------------
__device__ __align__(16) float g_h[NN * 128];     // h = x @ W
__device__ __align__(16) float g_out[NN * 128];   // unnormalized aggregation acc (init = h)
__device__ __align__(16) float g_asrc[NN * 4];    // a_src per node/head
__device__ __align__(16) float g_dn[NN * 8];      // per dst node: {a_dst[4], e_loop[4]}
__device__ __align__(16) float g_s[NN * 4];       // softmax denominator acc (excl. self-loop's 1)

// smem layout (floats) for k_gemm
#define WS   0        // W tile            [128][128]
#define XS   16384    // X tile transposed [128][129]
#define INV  32896    // 1/(s+1) per (row,head)  [512]
#define ATTS 33408    // att_src [128]
#define ATTD 33536    // att_dst [128]
#define BSM  33664    // bias    [128]
#define SMF  33792    // total floats
#define SMB  (SMF * 4)

__device__ __forceinline__ float lrelu(float v) { return v > 0.f ? v : 0.2f * v; }

__device__ __forceinline__ void red_add_v4(float4* addr, float4 v) {
    asm volatile("red.global.add.v4.f32 [%0], {%1, %2, %3, %4};"
                 :: "l"(addr), "f"(v.x), "f"(v.y), "f"(v.z), "f"(v.w)
                 : "memory");
}
__device__ __forceinline__ void red_add_f32(float* addr, float v) {
    asm volatile("red.global.add.f32 [%0], %1;" :: "l"(addr), "f"(v) : "memory");
}

// ---------------- fused GEMM + prep (+ optional normalize-relu-bias prologue) -------
// FUSE_IN=false: X is raw input.
// FUSE_IN=true : X = g_out of previous layer; applies relu(X*inv(s+1)+bias_prev) on load.
// Epilogue: writes h to g_h AND g_out (self-loop init), computes a_src/a_dst/e_loop,
// zeroes g_s.  One 128-row tile per block; strictly row-partitioned => in-place safe.
template <bool FUSE_IN>
__global__ __launch_bounds__(256) void k_gemm(const float* __restrict__ X,
                                              const float* __restrict__ W,
                                              const float* __restrict__ att_s,
                                              const float* __restrict__ att_d,
                                              const float* __restrict__ bias_prev) {
    extern __shared__ float sm[];
    const int tx = threadIdx.x;          // 0..15 (col group)
    const int ty = threadIdx.y;          // 0..15 (row group)
    const int tid = ty * 16 + tx;
    const int row0 = blockIdx.x * 128;

    // phase 1: W, att vectors, and (fused) inv + bias
    const float4* W4 = (const float4*)W;
    float4* ws4 = (float4*)(sm + WS);
#pragma unroll 4
    for (int i = tid; i < 4096; i += 256) ws4[i] = W4[i];
    if (tid < 128) {
        sm[ATTS + tid] = att_s[tid];
        sm[ATTD + tid] = att_d[tid];
    }
    if (FUSE_IN) {
        if (tid < 128) sm[BSM + tid] = bias_prev[tid];
        for (int idx = tid; idx < 512; idx += 256) {
            int r = idx >> 2, row = row0 + r;
            float sv = (row < NN) ? g_s[row * 4 + (idx & 3)] : 0.f;
            sm[INV + idx] = 1.0f / (sv + 1.0f);
        }
        __syncthreads();   // inv/bias visible before X load
    }

    // phase 2: X tile transposed into xs[k*129+r]
    float* xs = sm + XS;
    for (int i = tid; i < 16384; i += 256) {
        int r = i >> 7, k = i & 127;
        int row = row0 + r;
        float v = 0.f;
        if (row < NN) {
            float raw = X[row * 128 + k];
            if (FUSE_IN)
                v = fmaxf(raw * sm[INV + r * 4 + (k >> 5)] + sm[BSM + k], 0.f);
            else
                v = raw;
        }
        xs[k * 129 + r] = v;
    }
    __syncthreads();

    // phase 3: main 128x128x128 FMA loop, 8x8 register tile
    float acc[8][8];
#pragma unroll
    for (int i = 0; i < 8; i++)
#pragma unroll
        for (int j = 0; j < 8; j++) acc[i][j] = 0.f;

    const int rb = ty * 8, cb = tx * 8;
    float* ws = sm + WS;
#pragma unroll 8
    for (int k = 0; k < 128; k++) {
        float xv[8];
#pragma unroll
        for (int i = 0; i < 8; i++) xv[i] = xs[k * 129 + rb + i];
        float4 w0 = *(const float4*)&ws[k * 128 + cb];
        float4 w1 = *(const float4*)&ws[k * 128 + cb + 4];
        float wv[8] = {w0.x, w0.y, w0.z, w0.w, w1.x, w1.y, w1.z, w1.w};
#pragma unroll
        for (int i = 0; i < 8; i++)
#pragma unroll
            for (int j = 0; j < 8; j++) acc[i][j] += xv[i] * wv[j];
    }

    // phase 4: store h (to both g_h and g_out) + attention partials
    float att_sv[8], att_dv[8];
#pragma unroll
    for (int j = 0; j < 8; j++) {
        att_sv[j] = sm[ATTS + cb + j];
        att_dv[j] = sm[ATTD + cb + j];
    }
    __syncthreads();   // done reading ws/xs; reuse sm[0..4096) for partials

#pragma unroll
    for (int i = 0; i < 8; i++) {
        int row = row0 + rb + i;
        float ps = 0.f, pd = 0.f;
#pragma unroll
        for (int j = 0; j < 8; j++) {
            ps += acc[i][j] * att_sv[j];
            pd += acc[i][j] * att_dv[j];
        }
        sm[(rb + i) * 16 + tx] = ps;
        sm[2048 + (rb + i) * 16 + tx] = pd;
        if (row < NN) {
            float4 o0 = {acc[i][0], acc[i][1], acc[i][2], acc[i][3]};
            float4 o1 = {acc[i][4], acc[i][5], acc[i][6], acc[i][7]};
            *(float4*)&g_h[row * 128 + cb]       = o0;
            *(float4*)&g_h[row * 128 + cb + 4]   = o1;
            *(float4*)&g_out[row * 128 + cb]     = o0;
            *(float4*)&g_out[row * 128 + cb + 4] = o1;
        }
    }
    __syncthreads();

    // phase 5: reduce partials over 4 tx-groups per head; write a_src/a_dst/e_loop, zero s
    for (int idx = tid; idx < 512; idx += 256) {
        int r = idx >> 2, head = idx & 3;
        int row = row0 + r;
        if (row < NN) {
            float as = 0.f, ad = 0.f;
#pragma unroll
            for (int t = 0; t < 4; t++) {
                as += sm[r * 16 + head * 4 + t];
                ad += sm[2048 + r * 16 + head * 4 + t];
            }
            g_asrc[row * 4 + head]    = as;
            g_dn[row * 8 + head]      = ad;
            g_dn[row * 8 + 4 + head]  = lrelu(as + ad);
            g_s[row * 4 + head]       = 0.f;
        }
    }
}

// ---------------- edge pass: w = exp(lrelu(as+ad)-eloop); s += w; out += w*h ---------
__global__ void k_edge(const int* __restrict__ ei) {
    int t = blockIdx.x * blockDim.x + threadIdx.x;
    int e = t >> 5, lane = t & 31;
    if (e >= EE) return;
    int s = __ldg(ei + e), d = __ldg(ei + EE + e);
    int head = lane >> 3;

    float as = __ldg(&g_asrc[s * 4 + head]);
    float ad = __ldg(&g_dn[d * 8 + head]);
    float el = __ldg(&g_dn[d * 8 + 4 + head]);
    float w = __expf(lrelu(as + ad) - el);

    if ((lane & 7) == 0) red_add_f32(&g_s[d * 4 + head], w);

    float4 v = ((const float4*)g_h)[s * 32 + lane];
    v.x *= w; v.y *= w; v.z *= w; v.w *= w;
    red_add_v4(((float4*)g_out) + d * 32 + lane, v);
}

// ---------------- final layer only: d_out = relu(out/(s+1) + bias) ----------------
__global__ void k_finish(const float* __restrict__ bias, float* __restrict__ xout) {
    int idx = blockIdx.x * blockDim.x + threadIdx.x;
    if (idx >= NN * 32) return;
    int n = idx >> 5, q = idx & 31, head = q >> 3;
    float inv = 1.0f / (g_s[n * 4 + head] + 1.0f);
    float4 o = ((const float4*)g_out)[idx];
    float4 b = ((const float4*)bias)[q];
    o.x = fmaxf(o.x * inv + b.x, 0.f); o.y = fmaxf(o.y * inv + b.y, 0.f);
    o.z = fmaxf(o.z * inv + b.z, 0.f); o.w = fmaxf(o.w * inv + b.w, 0.f);
    ((float4*)xout)[idx] = o;
}

// ---------------- host ----------------
extern "C" void kernel_launch(void* const* d_in, const int* in_sizes, int n_in,
                              void* d_out, int out_size) {
    const float* x = nullptr;
    const int*   ei[3] = {};
    const float* W[3] = {};
    const float* small[9] = {};
    int nei = 0, nw = 0, ns = 0;
    for (int i = 0; i < n_in; i++) {
        int sz = in_sizes[i];
        if (sz == NN * 128)          x = (const float*)d_in[i];
        else if (sz == 2 * EE)       { if (nei < 3) ei[nei++] = (const int*)d_in[i]; }
        else if (sz == 128 * 128)    { if (nw < 3)  W[nw++]  = (const float*)d_in[i]; }
        else if (sz == 128)          { if (ns < 9)  small[ns++] = (const float*)d_in[i]; }
    }
    const float* asrc[3], *adst[3], *bias[3];
    for (int l = 0; l < 3; l++) {
        asrc[l] = small[l * 3 + 0];
        adst[l] = small[l * 3 + 1];
        bias[l] = small[l * 3 + 2];
    }

    float* outbuf = nullptr;
    cudaGetSymbolAddress((void**)&outbuf, g_out);
    cudaFuncSetAttribute(k_gemm<false>, cudaFuncAttributeMaxDynamicSharedMemorySize, SMB);
    cudaFuncSetAttribute(k_gemm<true>,  cudaFuncAttributeMaxDynamicSharedMemorySize, SMB);

    const int GEMM_BLOCKS = (NN + 127) / 128;       // 782
    const int EWARP = (EE * 32 + 255) / 256;        // warp per edge
    const int NELT  = (NN * 32 + 255) / 256;

    // layer 0
    k_gemm<false><<<GEMM_BLOCKS, dim3(16, 16), SMB>>>(x, W[0], asrc[0], adst[0], nullptr);
    k_edge<<<EWARP, 256>>>(ei[0]);
    // layer 1 (consumes g_out/g_s of layer 0, applies bias0)
    k_gemm<true><<<GEMM_BLOCKS, dim3(16, 16), SMB>>>(outbuf, W[1], asrc[1], adst[1], bias[0]);
    k_edge<<<EWARP, 256>>>(ei[1]);
    // layer 2
    k_gemm<true><<<GEMM_BLOCKS, dim3(16, 16), SMB>>>(outbuf, W[2], asrc[2], adst[2], bias[1]);
    k_edge<<<EWARP, 256>>>(ei[2]);
    // final normalize + bias + relu
    k_finish<<<NELT, 256>>>(bias[2], (float*)d_out);
}

// round 6
// speedup vs baseline: 1.7759x; 1.3920x over previous
#include <cuda_runtime.h>
#include <cstdint>

#define NN 100000
#define EE 800000
#define NB391 391           // ceil(100000/256)

typedef unsigned long long u64;

// ---------------- device scratch ----------------
__device__ __align__(16) float g_h[NN * 128];     // h = x @ W
__device__ __align__(16) float g_x1[NN * 128];    // inter-layer activations
__device__ __align__(16) float g_asrc[NN * 4];    // a_src per node/head
__device__ __align__(16) float g_dn[NN * 8];      // per dst node: {a_dst[4], e_loop[4]}
__device__ int g_deg[NN];
__device__ int g_off[NN];
__device__ int g_cur[NN];
__device__ int g_bsum[NB391];
__device__ int g_bpref[NB391];
__device__ int g_csr[EE];                         // src ids grouped by dst

// smem layout (floats) for k_gemm
// X tile row stride = 132 (16B-aligned row starts: 132*4=528 % 16 == 0)
#define XSTR 132
#define WS   0                      // W tile [128][128]
#define XS   16384                  // X tile transposed [128][XSTR]
#define ATTS (XS + 128 * XSTR)      // att_src [128]
#define ATTD (ATTS + 128)           // att_dst [128]
#define SMF  (ATTD + 128)
#define SMB  (SMF * 4)

__device__ __forceinline__ float lrelu(float v) { return v > 0.f ? v : 0.2f * v; }

__device__ __forceinline__ u64 pack2_dup(float x) {
    u64 r; asm("mov.b64 %0, {%1, %1};" : "=l"(r) : "f"(x)); return r;
}
__device__ __forceinline__ u64 ffma2(u64 a, u64 b, u64 c) {
    u64 d; asm("fma.rn.f32x2 %0, %1, %2, %3;" : "=l"(d) : "l"(a), "l"(b), "l"(c)); return d;
}
__device__ __forceinline__ float2 unpack2(u64 v) {
    float2 r; asm("mov.b64 {%0, %1}, %2;" : "=f"(r.x), "=f"(r.y) : "l"(v)); return r;
}

// ---------------- GEMM (f32x2 pipe) + attention epilogue ----------------
// writes g_h, g_asrc, g_dn. X is a plain [N,128] activation matrix.
__global__ __launch_bounds__(256) void k_gemm(const float* __restrict__ X,
                                              const float* __restrict__ W,
                                              const float* __restrict__ att_s,
                                              const float* __restrict__ att_d) {
    extern __shared__ float sm[];
    const int tx = threadIdx.x;          // 0..15 col group
    const int ty = threadIdx.y;          // 0..15 row group
    const int tid = ty * 16 + tx;
    const int row0 = blockIdx.x * 128;

    const float4* W4 = (const float4*)W;
    float4* ws4 = (float4*)(sm + WS);
#pragma unroll 4
    for (int i = tid; i < 4096; i += 256) ws4[i] = W4[i];
    if (tid < 128) {
        sm[ATTS + tid] = att_s[tid];
        sm[ATTD + tid] = att_d[tid];
    }
    float* xs = sm + XS;
    for (int i = tid; i < 16384; i += 256) {
        int r = i >> 7, k = i & 127;
        int row = row0 + r;
        xs[k * XSTR + r] = (row < NN) ? X[row * 128 + k] : 0.f;
    }
    __syncthreads();

    // 8x8 tile as 8x4 packed-pair accumulators
    u64 acc2[8][4];
#pragma unroll
    for (int i = 0; i < 8; i++)
#pragma unroll
        for (int j = 0; j < 4; j++) acc2[i][j] = 0ull;

    const int rb = ty * 8, cb = tx * 8;
    float* ws = sm + WS;
#pragma unroll 4
    for (int k = 0; k < 128; k++) {
        float4 xa = *(const float4*)&xs[k * XSTR + rb];       // 16B-aligned (XSTR=132)
        float4 xb = *(const float4*)&xs[k * XSTR + rb + 4];
        u64 xp[8] = {pack2_dup(xa.x), pack2_dup(xa.y), pack2_dup(xa.z), pack2_dup(xa.w),
                     pack2_dup(xb.x), pack2_dup(xb.y), pack2_dup(xb.z), pack2_dup(xb.w)};
        const u64* w8 = (const u64*)&ws[k * 128 + cb];        // 32B-aligned
        u64 wp0 = w8[0], wp1 = w8[1], wp2 = w8[2], wp3 = w8[3];
#pragma unroll
        for (int i = 0; i < 8; i++) {
            acc2[i][0] = ffma2(xp[i], wp0, acc2[i][0]);
            acc2[i][1] = ffma2(xp[i], wp1, acc2[i][1]);
            acc2[i][2] = ffma2(xp[i], wp2, acc2[i][2]);
            acc2[i][3] = ffma2(xp[i], wp3, acc2[i][3]);
        }
    }

    // unpack + attention partials + store h
    float att_sv[8], att_dv[8];
#pragma unroll
    for (int j = 0; j < 8; j++) {
        att_sv[j] = sm[ATTS + cb + j];
        att_dv[j] = sm[ATTD + cb + j];
    }
    __syncthreads();   // done with ws/xs; reuse sm[0..4096) for partials

#pragma unroll
    for (int i = 0; i < 8; i++) {
        float2 p0 = unpack2(acc2[i][0]), p1 = unpack2(acc2[i][1]);
        float2 p2 = unpack2(acc2[i][2]), p3 = unpack2(acc2[i][3]);
        float a[8] = {p0.x, p0.y, p1.x, p1.y, p2.x, p2.y, p3.x, p3.y};
        float ps = 0.f, pd = 0.f;
#pragma unroll
        for (int j = 0; j < 8; j++) {
            ps += a[j] * att_sv[j];
            pd += a[j] * att_dv[j];
        }
        sm[(rb + i) * 16 + tx] = ps;
        sm[2048 + (rb + i) * 16 + tx] = pd;
        int row = row0 + rb + i;
        if (row < NN) {
            *(float4*)&g_h[row * 128 + cb]     = make_float4(a[0], a[1], a[2], a[3]);
            *(float4*)&g_h[row * 128 + cb + 4] = make_float4(a[4], a[5], a[6], a[7]);
        }
    }
    __syncthreads();

    for (int idx = tid; idx < 512; idx += 256) {
        int r = idx >> 2, head = idx & 3;
        int row = row0 + r;
        if (row < NN) {
            float as = 0.f, ad = 0.f;
#pragma unroll
            for (int t = 0; t < 4; t++) {
                as += sm[r * 16 + head * 4 + t];
                ad += sm[2048 + r * 16 + head * 4 + t];
            }
            g_asrc[row * 4 + head]   = as;
            g_dn[row * 8 + head]     = ad;
            g_dn[row * 8 + 4 + head] = lrelu(as + ad);
        }
    }
}

// ---------------- CSR build ----------------
__global__ void k_zero_deg() {
    int i = blockIdx.x * blockDim.x + threadIdx.x;
    if (i < NN) g_deg[i] = 0;
}
__global__ void k_hist(const int* __restrict__ ei) {
    int e = blockIdx.x * blockDim.x + threadIdx.x;
    if (e < EE) atomicAdd(&g_deg[__ldg(ei + EE + e)], 1);
}

__device__ __forceinline__ int block_exscan(int v, int* smw, int tid, int nthreads) {
    int lane = tid & 31, wid = tid >> 5;
    int x = v;
#pragma unroll
    for (int o = 1; o < 32; o <<= 1) {
        int y = __shfl_up_sync(0xffffffff, x, o);
        if (lane >= o) x += y;
    }
    if (lane == 31) smw[wid] = x;
    __syncthreads();
    if (wid == 0) {
        int nw = nthreads >> 5;
        int t = (lane < nw) ? smw[lane] : 0;
#pragma unroll
        for (int o = 1; o < 32; o <<= 1) {
            int y = __shfl_up_sync(0xffffffff, t, o);
            if (lane >= o) t += y;
        }
        if (lane < nw) smw[lane] = t;   // inclusive warp totals
    }
    __syncthreads();
    int base = (wid > 0) ? smw[wid - 1] : 0;
    return base + x - v;                // exclusive
}

__global__ void k_scan1() {
    __shared__ int smw[32];
    int tid = threadIdx.x;
    int i = blockIdx.x * 256 + tid;
    int v = (i < NN) ? g_deg[i] : 0;
    int ex = block_exscan(v, smw, tid, 256);
    if (i < NN) g_off[i] = ex;
    if (tid == 255) g_bsum[blockIdx.x] = ex + v;
}
__global__ void k_scan2() {
    __shared__ int smw[32];
    int tid = threadIdx.x;
    int v = (tid < NB391) ? g_bsum[tid] : 0;
    int ex = block_exscan(v, smw, tid, 512);
    if (tid < NB391) g_bpref[tid] = ex;
}
__global__ void k_scan3() {
    int tid = threadIdx.x;
    int i = blockIdx.x * 256 + tid;
    if (i < NN) {
        int o = g_off[i] + g_bpref[blockIdx.x];
        g_off[i] = o;
        g_cur[i] = o;
    }
}
__global__ void k_fill(const int* __restrict__ ei) {
    int e = blockIdx.x * blockDim.x + threadIdx.x;
    if (e >= EE) return;
    int s = __ldg(ei + e), d = __ldg(ei + EE + e);
    int pos = atomicAdd(&g_cur[d], 1);
    g_csr[pos] = s;
}

// ---------------- aggregation: one warp per dst node, no atomics ----------------
// out[d] = relu( (h[d] + sum_e w_e * h[src_e]) / (1 + sum_e w_e) + bias )
__global__ __launch_bounds__(256) void k_agg(const float* __restrict__ bias,
                                             float* __restrict__ xout) {
    int t = blockIdx.x * blockDim.x + threadIdx.x;
    int d = t >> 5, lane = t & 31;
    if (d >= NN) return;
    int head = lane >> 3;

    float ad = __ldg(&g_dn[d * 8 + head]);
    float el = __ldg(&g_dn[d * 8 + 4 + head]);

    const float4* h4 = (const float4*)g_h;
    float4 acc = h4[d * 32 + lane];     // self-loop message (weight 1)
    float ssum = 1.0f;

    int p = g_off[d];
    int end = p + g_deg[d];
    for (; p + 1 < end; p += 2) {
        int s0 = __ldg(&g_csr[p]);
        int s1 = __ldg(&g_csr[p + 1]);
        float as0 = __ldg(&g_asrc[s0 * 4 + head]);
        float as1 = __ldg(&g_asrc[s1 * 4 + head]);
        float4 v0 = h4[s0 * 32 + lane];
        float4 v1 = h4[s1 * 32 + lane];
        float w0 = __expf(lrelu(as0 + ad) - el);
        float w1 = __expf(lrelu(as1 + ad) - el);
        acc.x += w0 * v0.x + w1 * v1.x;
        acc.y += w0 * v0.y + w1 * v1.y;
        acc.z += w0 * v0.z + w1 * v1.z;
        acc.w += w0 * v0.w + w1 * v1.w;
        ssum += w0 + w1;
    }
    if (p < end) {
        int s0 = __ldg(&g_csr[p]);
        float as0 = __ldg(&g_asrc[s0 * 4 + head]);
        float4 v0 = h4[s0 * 32 + lane];
        float w0 = __expf(lrelu(as0 + ad) - el);
        acc.x += w0 * v0.x; acc.y += w0 * v0.y;
        acc.z += w0 * v0.z; acc.w += w0 * v0.w;
        ssum += w0;
    }

    float inv = 1.0f / ssum;
    float4 b = __ldg(((const float4*)bias) + lane);
    acc.x = fmaxf(acc.x * inv + b.x, 0.f);
    acc.y = fmaxf(acc.y * inv + b.y, 0.f);
    acc.z = fmaxf(acc.z * inv + b.z, 0.f);
    acc.w = fmaxf(acc.w * inv + b.w, 0.f);
    ((float4*)xout)[d * 32 + lane] = acc;
}

// ---------------- host ----------------
extern "C" void kernel_launch(void* const* d_in, const int* in_sizes, int n_in,
                              void* d_out, int out_size) {
    const float* x = nullptr;
    const int*   ei[3] = {};
    const float* W[3] = {};
    const float* small[9] = {};
    int nei = 0, nw = 0, ns = 0;
    for (int i = 0; i < n_in; i++) {
        int sz = in_sizes[i];
        if (sz == NN * 128)          x = (const float*)d_in[i];
        else if (sz == 2 * EE)       { if (nei < 3) ei[nei++] = (const int*)d_in[i]; }
        else if (sz == 128 * 128)    { if (nw < 3)  W[nw++]  = (const float*)d_in[i]; }
        else if (sz == 128)          { if (ns < 9)  small[ns++] = (const float*)d_in[i]; }
    }
    const float* asrc[3], *adst[3], *bias[3];
    for (int l = 0; l < 3; l++) {
        asrc[l] = small[l * 3 + 0];
        adst[l] = small[l * 3 + 1];
        bias[l] = small[l * 3 + 2];
    }

    float* x1 = nullptr;
    cudaGetSymbolAddress((void**)&x1, g_x1);
    cudaFuncSetAttribute(k_gemm, cudaFuncAttributeMaxDynamicSharedMemorySize, SMB);

    const int GEMM_BLOCKS = (NN + 127) / 128;     // 782
    const int EB   = (EE + 255) / 256;            // 3125
    const int AGGB = (NN * 32 + 255) / 256;       // 12500

    const float* xin = x;
    for (int l = 0; l < 3; l++) {
        float* xout = (l == 2) ? (float*)d_out : x1;
        k_gemm<<<GEMM_BLOCKS, dim3(16, 16), SMB>>>(xin, W[l], asrc[l], adst[l]);
        k_zero_deg<<<NB391, 256>>>();
        k_hist<<<EB, 256>>>(ei[l]);
        k_scan1<<<NB391, 256>>>();
        k_scan2<<<1, 512>>>();
        k_scan3<<<NB391, 256>>>();
        k_fill<<<EB, 256>>>(ei[l]);
        k_agg<<<AGGB, 256>>>(bias[l], xout);
        xin = xout;
    }
}

// round 7
// speedup vs baseline: 1.8106x; 1.0195x over previous
#include <cuda_runtime.h>
#include <cstdint>

#define NN 100000
#define EE 800000
#define N3 (3 * NN)                 // 300000 combined counters
#define SC1B 586                    // ceil(300000/512)

typedef unsigned long long u64;

// ---------------- device scratch ----------------
__device__ __align__(16) float g_h[NN * 128];     // h = x @ W
__device__ __align__(16) float g_x1[NN * 128];    // inter-layer activations
__device__ __align__(16) float g_asrc[NN * 4];    // a_src per node/head
__device__ __align__(16) float g_dn[NN * 8];      // per dst node: {a_dst[4], e_loop[4]}
__device__ int g_deg[N3];
__device__ int g_off[N3];
__device__ int g_cur[N3];
__device__ int g_bsum[SC1B];
__device__ int g_bpref[SC1B];
__device__ int g_csr[3 * EE];                     // src ids grouped by (layer,dst)

// smem layout (floats) for k_gemm; X tile stride 132 (16B-aligned rows)
#define XSTR 132
#define WS   0
#define XS   16384
#define ATTS (XS + 128 * XSTR)
#define ATTD (ATTS + 128)
#define SMF  (ATTD + 128)
#define SMB  (SMF * 4)

__device__ __forceinline__ float lrelu(float v) { return v > 0.f ? v : 0.2f * v; }

__device__ __forceinline__ u64 pack2_dup(float x) {
    u64 r; asm("mov.b64 %0, {%1, %1};" : "=l"(r) : "f"(x)); return r;
}
__device__ __forceinline__ u64 ffma2(u64 a, u64 b, u64 c) {
    u64 d; asm("fma.rn.f32x2 %0, %1, %2, %3;" : "=l"(d) : "l"(a), "l"(b), "l"(c)); return d;
}
__device__ __forceinline__ float2 unpack2(u64 v) {
    float2 r; asm("mov.b64 {%0, %1}, %2;" : "=f"(r.x), "=f"(r.y) : "l"(v)); return r;
}

// ---------------- GEMM (f32x2 pipe) + attention epilogue ----------------
__global__ __launch_bounds__(256) void k_gemm(const float* __restrict__ X,
                                              const float* __restrict__ W,
                                              const float* __restrict__ att_s,
                                              const float* __restrict__ att_d) {
    extern __shared__ float sm[];
    const int tx = threadIdx.x;          // 0..15 col group
    const int ty = threadIdx.y;          // 0..15 row group
    const int tid = ty * 16 + tx;
    const int row0 = blockIdx.x * 128;

    const float4* W4 = (const float4*)W;
    float4* ws4 = (float4*)(sm + WS);
#pragma unroll 4
    for (int i = tid; i < 4096; i += 256) ws4[i] = W4[i];
    if (tid < 128) {
        sm[ATTS + tid] = att_s[tid];
        sm[ATTD + tid] = att_d[tid];
    }
    float* xs = sm + XS;
    for (int i = tid; i < 16384; i += 256) {
        int r = i >> 7, k = i & 127;
        int row = row0 + r;
        xs[k * XSTR + r] = (row < NN) ? X[row * 128 + k] : 0.f;
    }
    __syncthreads();

    u64 acc2[8][4];
#pragma unroll
    for (int i = 0; i < 8; i++)
#pragma unroll
        for (int j = 0; j < 4; j++) acc2[i][j] = 0ull;

    const int rb = ty * 8, cb = tx * 8;
    float* ws = sm + WS;
#pragma unroll 4
    for (int k = 0; k < 128; k++) {
        float4 xa = *(const float4*)&xs[k * XSTR + rb];
        float4 xb = *(const float4*)&xs[k * XSTR + rb + 4];
        u64 xp[8] = {pack2_dup(xa.x), pack2_dup(xa.y), pack2_dup(xa.z), pack2_dup(xa.w),
                     pack2_dup(xb.x), pack2_dup(xb.y), pack2_dup(xb.z), pack2_dup(xb.w)};
        const u64* w8 = (const u64*)&ws[k * 128 + cb];
        u64 wp0 = w8[0], wp1 = w8[1], wp2 = w8[2], wp3 = w8[3];
#pragma unroll
        for (int i = 0; i < 8; i++) {
            acc2[i][0] = ffma2(xp[i], wp0, acc2[i][0]);
            acc2[i][1] = ffma2(xp[i], wp1, acc2[i][1]);
            acc2[i][2] = ffma2(xp[i], wp2, acc2[i][2]);
            acc2[i][3] = ffma2(xp[i], wp3, acc2[i][3]);
        }
    }

    float att_sv[8], att_dv[8];
#pragma unroll
    for (int j = 0; j < 8; j++) {
        att_sv[j] = sm[ATTS + cb + j];
        att_dv[j] = sm[ATTD + cb + j];
    }
    __syncthreads();   // done with ws/xs; reuse sm[0..4096) for partials

#pragma unroll
    for (int i = 0; i < 8; i++) {
        float2 p0 = unpack2(acc2[i][0]), p1 = unpack2(acc2[i][1]);
        float2 p2 = unpack2(acc2[i][2]), p3 = unpack2(acc2[i][3]);
        float a[8] = {p0.x, p0.y, p1.x, p1.y, p2.x, p2.y, p3.x, p3.y};
        float ps = 0.f, pd = 0.f;
#pragma unroll
        for (int j = 0; j < 8; j++) {
            ps += a[j] * att_sv[j];
            pd += a[j] * att_dv[j];
        }
        sm[(rb + i) * 16 + tx] = ps;
        sm[2048 + (rb + i) * 16 + tx] = pd;
        int row = row0 + rb + i;
        if (row < NN) {
            *(float4*)&g_h[row * 128 + cb]     = make_float4(a[0], a[1], a[2], a[3]);
            *(float4*)&g_h[row * 128 + cb + 4] = make_float4(a[4], a[5], a[6], a[7]);
        }
    }
    __syncthreads();

    for (int idx = tid; idx < 512; idx += 256) {
        int r = idx >> 2, head = idx & 3;
        int row = row0 + r;
        if (row < NN) {
            float as = 0.f, ad = 0.f;
#pragma unroll
            for (int t = 0; t < 4; t++) {
                as += sm[r * 16 + head * 4 + t];
                ad += sm[2048 + r * 16 + head * 4 + t];
            }
            g_asrc[row * 4 + head]   = as;
            g_dn[row * 8 + head]     = ad;
            g_dn[row * 8 + 4 + head] = lrelu(as + ad);
        }
    }
}

// ---------------- fused 3-layer CSR build ----------------
__global__ void k_hist3(const int* __restrict__ e0, const int* __restrict__ e1,
                        const int* __restrict__ e2) {
    int e = blockIdx.x * blockDim.x + threadIdx.x;
    if (e >= EE) return;
    const int* ei = (blockIdx.y == 0) ? e0 : (blockIdx.y == 1) ? e1 : e2;
    atomicAdd(&g_deg[blockIdx.y * NN + __ldg(ei + EE + e)], 1);
}

__device__ __forceinline__ int block_exscan(int v, int* smw, int tid, int nthreads) {
    int lane = tid & 31, wid = tid >> 5;
    int x = v;
#pragma unroll
    for (int o = 1; o < 32; o <<= 1) {
        int y = __shfl_up_sync(0xffffffff, x, o);
        if (lane >= o) x += y;
    }
    if (lane == 31) smw[wid] = x;
    __syncthreads();
    if (wid == 0) {
        int nw = nthreads >> 5;
        int t = (lane < nw) ? smw[lane] : 0;
#pragma unroll
        for (int o = 1; o < 32; o <<= 1) {
            int y = __shfl_up_sync(0xffffffff, t, o);
            if (lane >= o) t += y;
        }
        if (lane < nw) smw[lane] = t;   // inclusive warp totals
    }
    __syncthreads();
    int base = (wid > 0) ? smw[wid - 1] : 0;
    return base + x - v;                // exclusive
}

__global__ void k_scan1() {
    __shared__ int smw[32];
    int tid = threadIdx.x;
    int i = blockIdx.x * 512 + tid;
    int v = (i < N3) ? g_deg[i] : 0;
    int ex = block_exscan(v, smw, tid, 512);
    if (i < N3) g_off[i] = ex;
    if (tid == 511) g_bsum[blockIdx.x] = ex + v;
}
__global__ void k_scan2() {
    __shared__ int smw[32];
    int tid = threadIdx.x;
    int v = (tid < SC1B) ? g_bsum[tid] : 0;
    int ex = block_exscan(v, smw, tid, 1024);
    if (tid < SC1B) g_bpref[tid] = ex;
}
__global__ void k_scan3() {
    int tid = threadIdx.x;
    int i = blockIdx.x * 512 + tid;
    if (i < N3) {
        int o = g_off[i] + g_bpref[blockIdx.x];
        g_off[i] = o;
        g_cur[i] = o;
    }
}
__global__ void k_fill3(const int* __restrict__ e0, const int* __restrict__ e1,
                        const int* __restrict__ e2) {
    int e = blockIdx.x * blockDim.x + threadIdx.x;
    if (e >= EE) return;
    const int* ei = (blockIdx.y == 0) ? e0 : (blockIdx.y == 1) ? e1 : e2;
    int s = __ldg(ei + e), d = __ldg(ei + EE + e);
    int pos = atomicAdd(&g_cur[blockIdx.y * NN + d], 1);
    g_csr[pos] = s;
}

// ---------------- aggregation: one warp per dst node, no atomics ----------------
__global__ __launch_bounds__(256) void k_agg(const float* __restrict__ bias,
                                             float* __restrict__ xout, int base) {
    int t = blockIdx.x * blockDim.x + threadIdx.x;
    int d = t >> 5, lane = t & 31;
    if (d >= NN) return;
    int head = lane >> 3;

    float ad = __ldg(&g_dn[d * 8 + head]);
    float el = __ldg(&g_dn[d * 8 + 4 + head]);

    const float4* h4 = (const float4*)g_h;
    float4 acc = h4[d * 32 + lane];     // self-loop message (weight 1)
    float ssum = 1.0f;

    int p = g_off[base + d];
    int end = p + g_deg[base + d];
    for (; p + 1 < end; p += 2) {
        int s0 = __ldg(&g_csr[p]);
        int s1 = __ldg(&g_csr[p + 1]);
        float as0 = __ldg(&g_asrc[s0 * 4 + head]);
        float as1 = __ldg(&g_asrc[s1 * 4 + head]);
        float4 v0 = h4[s0 * 32 + lane];
        float4 v1 = h4[s1 * 32 + lane];
        float w0 = __expf(lrelu(as0 + ad) - el);
        float w1 = __expf(lrelu(as1 + ad) - el);
        acc.x += w0 * v0.x + w1 * v1.x;
        acc.y += w0 * v0.y + w1 * v1.y;
        acc.z += w0 * v0.z + w1 * v1.z;
        acc.w += w0 * v0.w + w1 * v1.w;
        ssum += w0 + w1;
    }
    if (p < end) {
        int s0 = __ldg(&g_csr[p]);
        float as0 = __ldg(&g_asrc[s0 * 4 + head]);
        float4 v0 = h4[s0 * 32 + lane];
        float w0 = __expf(lrelu(as0 + ad) - el);
        acc.x += w0 * v0.x; acc.y += w0 * v0.y;
        acc.z += w0 * v0.z; acc.w += w0 * v0.w;
        ssum += w0;
    }

    float inv = 1.0f / ssum;
    float4 b = __ldg(((const float4*)bias) + lane);
    acc.x = fmaxf(acc.x * inv + b.x, 0.f);
    acc.y = fmaxf(acc.y * inv + b.y, 0.f);
    acc.z = fmaxf(acc.z * inv + b.z, 0.f);
    acc.w = fmaxf(acc.w * inv + b.w, 0.f);
    ((float4*)xout)[d * 32 + lane] = acc;
}

// ---------------- host ----------------
extern "C" void kernel_launch(void* const* d_in, const int* in_sizes, int n_in,
                              void* d_out, int out_size) {
    const float* x = nullptr;
    const int*   ei[3] = {};
    const float* W[3] = {};
    const float* small[9] = {};
    int nei = 0, nw = 0, ns = 0;
    for (int i = 0; i < n_in; i++) {
        int sz = in_sizes[i];
        if (sz == NN * 128)          x = (const float*)d_in[i];
        else if (sz == 2 * EE)       { if (nei < 3) ei[nei++] = (const int*)d_in[i]; }
        else if (sz == 128 * 128)    { if (nw < 3)  W[nw++]  = (const float*)d_in[i]; }
        else if (sz == 128)          { if (ns < 9)  small[ns++] = (const float*)d_in[i]; }
    }
    const float* asrc[3], *adst[3], *bias[3];
    for (int l = 0; l < 3; l++) {
        asrc[l] = small[l * 3 + 0];
        adst[l] = small[l * 3 + 1];
        bias[l] = small[l * 3 + 2];
    }

    float* x1 = nullptr;
    void* degp = nullptr;
    cudaGetSymbolAddress((void**)&x1, g_x1);
    cudaGetSymbolAddress(&degp, g_deg);
    cudaFuncSetAttribute(k_gemm, cudaFuncAttributeMaxDynamicSharedMemorySize, SMB);

    const int GEMM_BLOCKS = (NN + 127) / 128;     // 782
    const int EB   = (EE + 255) / 256;            // 3125
    const int AGGB = (NN * 32 + 255) / 256;       // 12500

    // fused CSR build for all 3 layers (independent of GEMM/agg)
    cudaMemsetAsync(degp, 0, N3 * sizeof(int));
    k_hist3<<<dim3(EB, 3), 256>>>(ei[0], ei[1], ei[2]);
    k_scan1<<<SC1B, 512>>>();
    k_scan2<<<1, 1024>>>();
    k_scan3<<<SC1B, 512>>>();
    k_fill3<<<dim3(EB, 3), 256>>>(ei[0], ei[1], ei[2]);

    const float* xin = x;
    for (int l = 0; l < 3; l++) {
        float* xout = (l == 2) ? (float*)d_out : x1;
        k_gemm<<<GEMM_BLOCKS, dim3(16, 16), SMB>>>(xin, W[l], asrc[l], adst[l]);
        k_agg<<<AGGB, 256>>>(bias[l], xout, l * NN);
        xin = xout;
    }
}